// round 5
// baseline (speedup 1.0000x reference)
#include <cuda_runtime.h>
#include <math.h>

#define LL 256
#define MAXB 512
#define NC 16            // chunks per sample (16 rows each)
#define CROWS 16
#define CHUNK_V4 1024    // 16*256/4 float4 per chunk

// ---- device-global scratch (allocation-free, graph-replay safe:
//      counters are reset by their last user each launch) ----
__device__ float g_psum [MAXB][NC];
__device__ float g_pgsum[MAXB][NC];
__device__ int   g_pany [MAXB][NC];
__device__ unsigned char g_rowflag[MAXB][LL];       // chunk ch owns rows [ch*16, ch*16+16)
__device__ unsigned char g_colflag[MAXB][NC][LL];
__device__ int   g_cnt[MAXB];                        // zero-init; reset by last chunk block
__device__ float g_total;                            // zero-init; reset by final block
__device__ int   g_nfin;                             // zero-init; reset by final block

__global__ void __launch_bounds__(256)
fused_loss(const float* __restrict__ Yp, const float* __restrict__ Yg,
           float* __restrict__ out, int B)
{
    const int blk = blockIdx.x;
    const int b   = blk >> 4;
    const int ch  = blk & 15;
    const int t   = threadIdx.x;
    const unsigned full = 0xffffffffu;
    const int warp = t >> 5, lane = t & 31;

    __shared__ unsigned char rflag[CROWS];
    __shared__ unsigned char cflag[LL];
    __shared__ float swp[8], swpg[8];
    __shared__ int   sanyw[8];
    __shared__ int   s_last;

    if (t < CROWS) rflag[t] = 0;
    cflag[t] = 0;
    __syncthreads();

    // ---------------- streaming phase: this chunk's 16x256 slab ----------------
    const float4* __restrict__ p4 =
        (const float4*)(Yp + (size_t)b * (LL * LL) + ch * (CROWS * LL));
    const float4* __restrict__ g4 =
        (const float4*)(Yg + (size_t)b * (LL * LL) + ch * (CROWS * LL));

    float sp = 0.f, spg = 0.f;
    float gmax = 0.f;
    #pragma unroll 2
    for (int i = t; i < CHUNK_V4; i += 256) {
        float4 v = __ldcs(p4 + i);
        float4 g = __ldcs(g4 + i);
        sp  += (v.x + v.y) + (v.z + v.w);
        spg += g.x * v.x + g.y * v.y + g.z * v.z + g.w * v.w;
        gmax = fmaxf(gmax, fmaxf(fmaxf(g.x, g.y), fmaxf(g.z, g.w)));

        float m = fmaxf(fmaxf(v.x, v.y), fmaxf(v.z, v.w));
        if (m > 0.5f) {                      // rare slow path (blob only)
            int pix = i << 2;
            rflag[pix >> 8] = 1;             // row within chunk
            int c0 = pix & 255;
            if (v.x > 0.5f) cflag[c0]     = 1;
            if (v.y > 0.5f) cflag[c0 + 1] = 1;
            if (v.z > 0.5f) cflag[c0 + 2] = 1;
            if (v.w > 0.5f) cflag[c0 + 3] = 1;
        }
    }

    // block reduction (8 warps)
    int any = (gmax > 0.f) ? 1 : 0;
    #pragma unroll
    for (int o = 16; o > 0; o >>= 1) {
        sp  += __shfl_down_sync(full, sp, o);
        spg += __shfl_down_sync(full, spg, o);
    }
    any = __any_sync(full, any);
    if (lane == 0) { swp[warp] = sp; swpg[warp] = spg; sanyw[warp] = any; }
    __syncthreads();

    if (t == 0) {
        float a = 0.f, c = 0.f; int an = 0;
        #pragma unroll
        for (int w = 0; w < 8; w++) { a += swp[w]; c += swpg[w]; an |= sanyw[w]; }
        g_psum [b][ch] = a;
        g_pgsum[b][ch] = c;
        g_pany [b][ch] = an;
    }
    if (t < CROWS) g_rowflag[b][ch * CROWS + t] = rflag[t];
    g_colflag[b][ch][t] = cflag[t];
    __syncthreads();                       // all partial writes issued

    // ---------------- last chunk block of this sample finishes it -------------
    if (t == 0) {
        __threadfence();
        int c = atomicAdd(&g_cnt[b], 1);
        s_last = (c == NC - 1);
        if (s_last) {
            __threadfence();
            g_cnt[b] = 0;                  // reset for next graph replay
        }
    }
    __syncthreads();
    if (!s_last) return;

    __shared__ int sMinR, sMaxR, sMinC, sMaxC;
    __shared__ float sSum, sPos;
    __shared__ int   sAny;
    __shared__ float sw[8];

    if (t == 0) {
        sMinR = LL; sMaxR = -1; sMinC = LL; sMaxC = -1;
        float a = 0.f, c = 0.f; int an = 0;
        #pragma unroll
        for (int k = 0; k < NC; k++) { a += g_psum[b][k]; c += g_pgsum[b][k]; an |= g_pany[b][k]; }
        sSum = a; sPos = c; sAny = an;
    }
    __syncthreads();

    if (g_rowflag[b][t]) { atomicMin(&sMinR, t); atomicMax(&sMaxR, t); }
    unsigned char cf = 0;
    #pragma unroll
    for (int k = 0; k < NC; k++) cf |= g_colflag[b][k][t];
    if (cf) { atomicMin(&sMinC, t); atomicMax(&sMaxC, t); }
    __syncthreads();

    const float sumYp = sSum;
    float positive;

    if (sAny) {
        positive = sPos;
    } else {
        int left, right, up, down;
        if (sMaxR < 0) { left = 0; right = 0; }
        else           { left = sMinR; right = (LL - 1) - sMaxR; }
        if (sMaxC < 0) { up = 0; down = 0; }
        else           { up = sMinC; down = (LL - 1) - sMaxC; }
        int x_r = (right - left) >> 1;     // floor division, matches //2
        int y_r = (down  - up)   >> 1;
        float gt0 = (float)(left + x_r);   // vs column coord
        float gt1 = (float)(up   + y_r);   // vs row coord

        float acc = 0.f;
        if (x_r != 0 && y_r != 0) {
            // h>0.1  <=>  d0^4+d1^4 < ln(10)*(4/9) => |d0|,|d1| < ~1.006
            float hx = fabsf((float)x_r) * 1.01f + 1.5f;
            float hy = fabsf((float)y_r) * 1.01f + 1.5f;
            int c0 = max(0, (int)floorf(gt0 - hx));
            int c1 = min(LL - 1, (int)ceilf(gt0 + hx));
            int r0 = max(0, (int)floorf(gt1 - hy));
            int r1 = min(LL - 1, (int)ceilf(gt1 + hy));
            int W = c1 - c0 + 1;
            int n = W * (r1 - r0 + 1);
            const float denom = 0.44444445f;   // f32((2/3)^2)
            const float* __restrict__ base = Yp + (size_t)b * (LL * LL);
            for (int i = t; i < n; i += 256) {
                int r = r0 + i / W;
                int c = c0 + i % W;
                float d0 = ((float)c - gt0) / (float)x_r;
                float d1 = ((float)r - gt1) / (float)y_r;
                float d02 = d0 * d0, d12 = d1 * d1;
                float s = d02 * d02 + d12 * d12;
                float h = expf(-s / denom);
                if (h > 0.1f) acc += base[r * LL + c];
            }
        }
        #pragma unroll
        for (int o = 16; o > 0; o >>= 1) acc += __shfl_down_sync(full, acc, o);
        if (lane == 0) sw[warp] = acc;
        __syncthreads();
        float tot = 0.f;
        if (t == 0) {
            #pragma unroll
            for (int w = 0; w < 8; w++) tot += sw[w];
        }
        positive = tot;   // only thread 0's value is used below
    }

    // ---------------- global accumulation + final log by last sample ----------
    if (t == 0) {
        float negative = sumYp - positive;
        float ratio = negative / (positive + 1e-6f);
        atomicAdd(&g_total, ratio);
        __threadfence();
        int n = atomicAdd(&g_nfin, 1);
        if (n == B - 1) {
            float total = atomicExch(&g_total, 0.f);   // read + reset
            atomicExch(&g_nfin, 0);                    // reset
            out[0] = (total == 0.f) ? 0.f : (logf(total) / (float)B);
        }
    }
}

extern "C" void kernel_launch(void* const* d_in, const int* in_sizes, int n_in,
                              void* d_out, int out_size)
{
    const float* Yp = (const float*)d_in[0];
    const float* Yg = (const float*)d_in[1];
    int B = in_sizes[0] / (LL * LL);
    if (B > MAXB) B = MAXB;

    fused_loss<<<B * NC, 256>>>(Yp, Yg, (float*)d_out, B);
}

// round 6
// speedup vs baseline: 1.0393x; 1.0393x over previous
#include <cuda_runtime.h>
#include <math.h>

#define LL 256
#define MAXB 512

// ---- device-global scratch (zero-init; reset by last user each launch) ----
__device__ float g_total;
__device__ int   g_nfin;

__global__ void __launch_bounds__(512, 4)
fused_loss(const float* __restrict__ Yp, const float* __restrict__ Yg,
           float* __restrict__ out, int B)
{
    const int b = blockIdx.x;
    const int t = threadIdx.x;
    const unsigned full = 0xffffffffu;
    const int warp = t >> 5, lane = t & 31;

    const float4* __restrict__ p4 = (const float4*)(Yp + (size_t)b * (LL * LL));
    const float4* __restrict__ g4 = (const float4*)(Yg + (size_t)b * (LL * LL));

    // ---------------- pure-register streaming pass ----------------
    // float4 index i = t + 512*j  =>  pixel columns are FIXED per thread:
    //   cols = {4t, 4t+1, 4t+2, 4t+3} mod 256; row = i>>6 varies with j.
    float sp = 0.f, spg = 0.f, gmax = 0.f;
    float cm0 = 0.f, cm1 = 0.f, cm2 = 0.f, cm3 = 0.f;
    int minR = LL, maxR = -1;

    #pragma unroll 4
    for (int i = t; i < LL * LL / 4; i += 512) {
        float4 v = p4[i];
        float4 g = g4[i];
        sp  += (v.x + v.y) + (v.z + v.w);
        spg += g.x * v.x + g.y * v.y + g.z * v.z + g.w * v.w;
        gmax = fmaxf(gmax, fmaxf(fmaxf(g.x, g.y), fmaxf(g.z, g.w)));
        cm0 = fmaxf(cm0, v.x); cm1 = fmaxf(cm1, v.y);
        cm2 = fmaxf(cm2, v.z); cm3 = fmaxf(cm3, v.w);
        float m = fmaxf(fmaxf(v.x, v.y), fmaxf(v.z, v.w));
        if (m > 0.5f) {                      // rare (blob rows only)
            int r = i >> 6;
            minR = min(minR, r);
            maxR = max(maxR, r);
        }
    }

    // ---------------- epilogue: block reductions ----------------
    __shared__ float ssp[16], sspg[16], sgm[16];
    __shared__ int   smnr[16], smxr[16];
    __shared__ unsigned colw[8];          // 256 column-flag bits
    __shared__ float shSum, shPos, shAcc[16];
    __shared__ int   shAny, shXr, shYr, shC0, shC1, shR0, shR1, shW, shN, shGen;
    __shared__ float shGt0, shGt1;

    if (t < 8) colw[t] = 0;
    __syncthreads();

    // column flag bits from per-slot maxes (columns fixed per thread)
    unsigned cb = (cm0 > 0.5f ? 1u : 0u) | (cm1 > 0.5f ? 2u : 0u) |
                  (cm2 > 0.5f ? 4u : 0u) | (cm3 > 0.5f ? 8u : 0u);
    if (cb) {
        int cbase = (t & 63) << 2;        // 4t mod 256
        atomicOr(&colw[cbase >> 5], cb << (cbase & 31));
    }

    #pragma unroll
    for (int o = 16; o > 0; o >>= 1) {
        sp   += __shfl_down_sync(full, sp, o);
        spg  += __shfl_down_sync(full, spg, o);
        gmax  = fmaxf(gmax, __shfl_down_sync(full, gmax, o));
        minR  = min(minR, __shfl_down_sync(full, minR, o));
        maxR  = max(maxR, __shfl_down_sync(full, maxR, o));
    }
    if (lane == 0) { ssp[warp] = sp; sspg[warp] = spg; sgm[warp] = gmax;
                     smnr[warp] = minR; smxr[warp] = maxR; }
    __syncthreads();

    if (t == 0) {
        float a = 0.f, c = 0.f, gm = 0.f;
        int mnr = LL, mxr = -1;
        #pragma unroll
        for (int w = 0; w < 16; w++) {
            a += ssp[w]; c += sspg[w]; gm = fmaxf(gm, sgm[w]);
            mnr = min(mnr, smnr[w]); mxr = max(mxr, smxr[w]);
        }
        shSum = a; shPos = c;
        int any = (gm > 0.f);
        shAny = any;
        shGen = 0;
        if (!any) {
            // min/max column from bitmaps
            int mnc = LL, mxc = -1;
            #pragma unroll
            for (int w = 0; w < 8; w++) {
                unsigned bits = colw[w];
                if (bits) {
                    mnc = min(mnc, (w << 5) + __ffs(bits) - 1);
                    mxc = max(mxc, (w << 5) + 31 - __clz(bits));
                }
            }
            int left, right, up, down;
            if (mxr < 0) { left = 0; right = 0; }
            else         { left = mnr; right = (LL - 1) - mxr; }
            if (mxc < 0) { up = 0; down = 0; }
            else         { up = mnc; down = (LL - 1) - mxc; }
            int x_r = (right - left) >> 1;    // floor div, matches //2
            int y_r = (down  - up)   >> 1;
            float gt0 = (float)(left + x_r);  // vs column coord
            float gt1 = (float)(up   + y_r);  // vs row coord
            if (x_r != 0 && y_r != 0) {
                // h>0.1 <=> d0^4+d1^4 < ln(10)*4/9 => |d0|,|d1| < ~1.006
                float hx = fabsf((float)x_r) * 1.01f + 1.5f;
                float hy = fabsf((float)y_r) * 1.01f + 1.5f;
                int c0 = max(0, (int)floorf(gt0 - hx));
                int c1 = min(LL - 1, (int)ceilf(gt0 + hx));
                int r0 = max(0, (int)floorf(gt1 - hy));
                int r1 = min(LL - 1, (int)ceilf(gt1 + hy));
                shC0 = c0; shC1 = c1; shR0 = r0; shR1 = r1;
                shW = c1 - c0 + 1;
                shN = (c1 - c0 + 1) * (r1 - r0 + 1);
                shXr = x_r; shYr = y_r; shGt0 = gt0; shGt1 = gt1;
                shGen = 1;
            }
        }
    }
    __syncthreads();

    float positive;
    if (shAny) {
        positive = shPos;
    } else if (!shGen) {
        positive = 0.f;                       // degenerate box -> empty mask
    } else {
        // exact reference mask over the only window where h can exceed 0.1
        const float denom = 0.44444445f;      // f32((2/3)^2)
        const float* __restrict__ base = Yp + (size_t)b * (LL * LL);
        const int W = shW, n = shN, c0 = shC0, r0 = shR0;
        const float gt0 = shGt0, gt1 = shGt1;
        const float xr = (float)shXr, yr = (float)shYr;
        float acc = 0.f;
        for (int i = t; i < n; i += 512) {
            int r = r0 + i / W;
            int c = c0 + i % W;
            float d0 = ((float)c - gt0) / xr;
            float d1 = ((float)r - gt1) / yr;
            float d02 = d0 * d0, d12 = d1 * d1;
            float s = d02 * d02 + d12 * d12;
            float h = expf(-s / denom);
            if (h > 0.1f) acc += base[r * LL + c];
        }
        #pragma unroll
        for (int o = 16; o > 0; o >>= 1) acc += __shfl_down_sync(full, acc, o);
        if (lane == 0) shAcc[warp] = acc;
        __syncthreads();
        float tot = 0.f;
        if (t == 0) {
            #pragma unroll
            for (int w = 0; w < 16; w++) tot += shAcc[w];
        }
        positive = tot;                        // only thread 0's value used
    }

    // ---------------- global accumulation + final log ----------------
    if (t == 0) {
        float negative = shSum - positive;
        float ratio = negative / (positive + 1e-6f);
        atomicAdd(&g_total, ratio);
        __threadfence();
        int nfin = atomicAdd(&g_nfin, 1);
        if (nfin == B - 1) {
            float total = atomicExch(&g_total, 0.f);   // read + reset
            atomicExch(&g_nfin, 0);                    // reset
            out[0] = (total == 0.f) ? 0.f : (logf(total) / (float)B);
        }
    }
}

extern "C" void kernel_launch(void* const* d_in, const int* in_sizes, int n_in,
                              void* d_out, int out_size)
{
    const float* Yp = (const float*)d_in[0];
    const float* Yg = (const float*)d_in[1];
    int B = in_sizes[0] / (LL * LL);
    if (B > MAXB) B = MAXB;

    fused_loss<<<B, 512>>>(Yp, Yg, (float*)d_out, B);
}